// round 12
// baseline (speedup 1.0000x reference)
#include <cuda_runtime.h>
#include <cuda_bf16.h>

// LandmarksLoss: mean((pred - true)^2), true = windowed 128x128 bell table.
//
// R12 (= R11 resubmit; previous round died on container infra, not kernel):
// R4's lean stream body unchanged; decomposition changed to a perfectly
// balanced single wave: grid = 148 SMs * 8 CTAs = 1184, each CTA owns a
// contiguous float4 range (size +-1), segmented at image boundaries (<=2
// segments, warp-uniform). Split scheme: stage1 partials + tiny stage2.

#define H_DIM     224
#define W_DIM     224
#define HW        (H_DIM * W_DIM)      // 50176
#define ROWF4     (W_DIM / 4)          // 56
#define NF4       (HW / 4)             // 12544 float4 per image
#define THREADS   256
#define NWARP     (THREADS / 32)
#define GRID      1184                 // 148 * 8 -> exactly 8 CTAs per SM
#define MAX_PART  4096
#define DELTA     128
#define HALF      64

__device__ float g_partials[MAX_PART];

__device__ __forceinline__ float blockReduce(float v, float* s)
{
    #pragma unroll
    for (int off = 16; off > 0; off >>= 1)
        v += __shfl_down_sync(0xFFFFFFFFu, v, off);
    const int lane = threadIdx.x & 31;
    const int wid  = threadIdx.x >> 5;
    if (lane == 0) s[wid] = v;
    __syncthreads();
    if (wid == 0) {
        v = (lane < NWARP) ? s[lane] : 0.0f;
        #pragma unroll
        for (int off = NWARP / 2; off > 0; off >>= 1)
            v += __shfl_down_sync(0xFFFFFFFFu, v, off);
    }
    return v;  // valid in thread 0
}

__global__ void __launch_bounds__(THREADS, 8)
landmarks_stage1(const float* __restrict__ pred,
                 const float* __restrict__ lm,
                 const float* __restrict__ bell,
                 int q, int r)
{
    const int c = blockIdx.x;
    // Contiguous balanced range of global float4 indices [start, end).
    const int start = c * q + min(c, r);
    const int end   = start + q + (c < r ? 1 : 0);

    const float4* base = reinterpret_cast<const float4*>(pred);

    float acc = 0.0f;

    int bl      = start / NF4;
    int seg_beg = start;

    while (seg_beg < end) {
        const int ibase   = bl * NF4;
        const int seg_end = min(end, ibase + NF4);

        // landmarks: [...,0]=y_r (cols), [...,1]=x_r (rows); jnp.round = rintf
        const int yr = (int)rintf(__ldg(&lm[2 * bl + 0]));
        const int xr = (int)rintf(__ldg(&lm[2 * bl + 1]));
        const int xoff = HALF - xr;   // bell row = h + xoff
        const int yoff = HALF - yr;   // bell col = w + yoff

        #pragma unroll 4
        for (int i = seg_beg + threadIdx.x; i < seg_end; i += THREADS) {
            const float4 p = __ldg(base + i);

            const int il = i - ibase;           // 0..12543 within image
            const int h  = il / ROWF4;
            const int w0 = (il - h * ROWF4) * 4;

            const int ix = h + xoff;
            const bool rowok = ((unsigned)ix < (unsigned)DELTA);
            const int iy0 = w0 + yoff;
            const float* brow = bell + ix * DELTA;

            float t0 = 0.0f, t1 = 0.0f, t2 = 0.0f, t3 = 0.0f;
            if (rowok) {
                if ((unsigned)(iy0 + 0) < (unsigned)DELTA) t0 = __ldg(&brow[iy0 + 0]);
                if ((unsigned)(iy0 + 1) < (unsigned)DELTA) t1 = __ldg(&brow[iy0 + 1]);
                if ((unsigned)(iy0 + 2) < (unsigned)DELTA) t2 = __ldg(&brow[iy0 + 2]);
                if ((unsigned)(iy0 + 3) < (unsigned)DELTA) t3 = __ldg(&brow[iy0 + 3]);
            }

            const float d0 = p.x - t0;
            const float d1 = p.y - t1;
            const float d2 = p.z - t2;
            const float d3 = p.w - t3;
            acc = fmaf(d0, d0, acc);
            acc = fmaf(d1, d1, acc);
            acc = fmaf(d2, d2, acc);
            acc = fmaf(d3, d3, acc);
        }

        seg_beg = seg_end;
        ++bl;
    }

    __shared__ float s[NWARP];
    const float bsum = blockReduce(acc, s);
    if (threadIdx.x == 0) g_partials[blockIdx.x] = bsum;
}

__global__ void __launch_bounds__(THREADS)
landmarks_stage2(float* __restrict__ out, int n_part, float inv_n)
{
    float acc = 0.0f;
    for (int i = threadIdx.x; i < n_part; i += THREADS)
        acc += g_partials[i];

    __shared__ float s[NWARP];
    const float t = blockReduce(acc, s);
    if (threadIdx.x == 0) out[0] = t * inv_n;
}

extern "C" void kernel_launch(void* const* d_in, const int* in_sizes, int n_in,
                              void* d_out, int out_size)
{
    const float* pred = (const float*)d_in[0];  // (B, L, 224, 224)
    const float* lm   = (const float*)d_in[1];  // (B, L, 2)
    const float* bell = (const float*)d_in[2];  // (128, 128)
    float* out = (float*)d_out;

    const int n_bl  = in_sizes[1] / 2;          // B*L = 1088
    const int tot4  = n_bl * NF4;               // total float4 count
    const int q     = tot4 / GRID;
    const int r     = tot4 - q * GRID;
    const float inv_n = 1.0f / ((float)n_bl * (float)HW);

    landmarks_stage1<<<GRID, THREADS>>>(pred, lm, bell, q, r);
    landmarks_stage2<<<1, THREADS>>>(out, GRID, inv_n);
}